// round 15
// baseline (speedup 1.0000x reference)
#include <cuda_runtime.h>
#include <cstdint>
#include <float.h>

#define B_ 128
#define H_ 14
#define W_ 14
#define C_ 512
#define C4_ (C_ / 4)
#define HW_ (H_ * W_)
#define ITERS_ 10
#define NCHUNK 14
#define CHUNKLEN 14   // 196 / 14

// Scratch (device globals: no allocs allowed)
__device__ float4 g_pbest4[B_ * NCHUNK * C4_];
__device__ unsigned int g_pidx4[B_ * NCHUNK * C4_];
__device__ unsigned int g_assign_words[(B_ * C_) / 4];
__device__ int g_arrive[B_];   // zero-init; self-resetting each launch

__device__ __forceinline__ unsigned long long keep_policy() {
    unsigned long long policy;
    asm("createpolicy.fractional.L2::evict_last.b64 %0, 1.0;" : "=l"(policy));
    return policy;
}

__device__ __forceinline__ float4 ldg_keep(const float4* p,
                                           unsigned long long policy) {
    float4 v;
    asm("ld.global.nc.L2::cache_hint.v4.f32 {%0,%1,%2,%3}, [%4], %5;"
        : "=f"(v.x), "=f"(v.y), "=f"(v.z), "=f"(v.w)
        : "l"(p), "l"(policy));
    return v;
}

// ---------------------------------------------------------------------------
// Fused kernel A+B: partial argmax (R11 form) + last-arriving CTA per batch
// runs the k-means on L2-hot partials. grid (B, NCHUNK) = 1792 x 128 threads.
// ---------------------------------------------------------------------------
__global__ __launch_bounds__(C4_) void argmax_kmeans_fused(
    const float4* __restrict__ in4)
{
    __shared__ int s_last;
    __shared__ int hist[HW_];
    __shared__ float sinit[4];
    __shared__ float scent[4];

    const int b = blockIdx.x;
    const int chunk = blockIdx.y;
    const int q = threadIdx.x;
    const unsigned long long pol = keep_policy();

    // ---- phase 1: partial argmax for this (b, chunk) tile ----
    const float4* base = in4 + ((size_t)b * HW_ + chunk * CHUNKLEN) * C4_ + q;
    float bx = -FLT_MAX, by = -FLT_MAX, bz = -FLT_MAX, bw = -FLT_MAX;
    int ix = 0, iy = 0, iz = 0, iw = 0;
#pragma unroll
    for (int i = 0; i < CHUNKLEN; i++) {
        const float4 v = ldg_keep(base + (size_t)i * C4_, pol);
        if (v.x > bx) { bx = v.x; ix = i; }
        if (v.y > by) { by = v.y; iy = i; }
        if (v.z > bz) { bz = v.z; iz = i; }
        if (v.w > bw) { bw = v.w; iw = i; }
    }
    const int o = (b * NCHUNK + chunk) * C4_ + q;
    g_pbest4[o] = make_float4(bx, by, bz, bw);
    g_pidx4[o] = (unsigned int)ix | ((unsigned int)iy << 8) |
                 ((unsigned int)iz << 16) | ((unsigned int)iw << 24);

    // ---- arrival protocol: last CTA of this batch runs the k-means ----
    __threadfence();  // release partials
    if (q == 0) {
        const int old = atomicAdd(&g_arrive[b], 1);
        s_last = (old == NCHUNK - 1);
        if (s_last) atomicExch(&g_arrive[b], 0);  // reset for next replay
    }
    __syncthreads();
    if (!s_last) return;
    __threadfence();  // acquire all 14 chunk partials

    // ---- phase 2: combine + histogram (128 threads, 4 channels each) ----
    if (q < HW_) hist[q] = 0;
    if (q + 128 < HW_) hist[q + 128] = 0;
    __syncthreads();

    const float* pbest = (const float*)g_pbest4;
    const unsigned char* pidx = (const unsigned char*)g_pidx4;

    float px[4], py[4];
#pragma unroll
    for (int j = 0; j < 4; j++) {
        const int c = q + 128 * j;
        float best = -FLT_MAX;
        int bestIdx = 0;
#pragma unroll
        for (int k = 0; k < NCHUNK; k++) {
            const int oo = (b * NCHUNK + k) * C_ + c;
            const float v = pbest[oo];
            if (v > best) { best = v; bestIdx = k * CHUNKLEN + (int)pidx[oo]; }
        }
        px[j] = (float)(bestIdx % W_);
        py[j] = (float)(bestIdx / W_);
        atomicAdd(&hist[bestIdx], 1);
    }
    if (q == 0) { sinit[0] = px[0]; sinit[1] = py[0]; }
    if (q == 1) { sinit[2] = px[0]; sinit[3] = py[0]; }
    __syncthreads();

    // ---- phase 3: warp-0 k-means on the 196-bin histogram (bit-exact) ----
    if (q < 32) {
        int cnt[7]; float hx[7], hy[7];
        int sx = 0, sy = 0;
#pragma unroll
        for (int j = 0; j < 7; j++) {
            const int bin = q * 7 + j;
            const int n = (bin < HW_) ? hist[bin] : 0;
            cnt[j] = n;
            hx[j] = (float)(bin % W_);
            hy[j] = (float)(bin / W_);
            sx += n * (bin % W_);
            sy += n * (bin / W_);
        }
        const int Sx = __reduce_add_sync(0xffffffffu, sx);
        const int Sy = __reduce_add_sync(0xffffffffu, sy);

        float c0x = sinit[0], c0y = sinit[1];
        float c1x = sinit[2], c1y = sinit[3];

        for (int it = 0; it < ITERS_; it++) {
            int s1x = 0, s1y = 0, n1 = 0;
#pragma unroll
            for (int j = 0; j < 7; j++) {
                const float dx0 = hx[j] - c0x, dy0 = hy[j] - c0y;
                const float dx1 = hx[j] - c1x, dy1 = hy[j] - c1y;
                const float d0 = dx0 * dx0 + dy0 * dy0;
                const float d1 = dx1 * dx1 + dy1 * dy1;
                const int m = (d1 < d0) ? cnt[j] : 0;
                n1 += m;
                s1x += m * (int)hx[j];
                s1y += m * (int)hy[j];
            }
            const int T1x = __reduce_add_sync(0xffffffffu, s1x);
            const int T1y = __reduce_add_sync(0xffffffffu, s1y);
            const int T1n = __reduce_add_sync(0xffffffffu, n1);

            const float inv1 = 1.0f / fmaxf((float)T1n, 1.0f);
            const float inv0 = 1.0f / fmaxf((float)(C_ - T1n), 1.0f);
            // reference swaps clusters each update
            c0x = (float)T1x * inv1; c0y = (float)T1y * inv1;
            c1x = (float)(Sx - T1x) * inv0; c1y = (float)(Sy - T1y) * inv0;
        }
        if (q == 0) { scent[0] = c0x; scent[1] = c0y; scent[2] = c1x; scent[3] = c1y; }
    }
    __syncthreads();

    // ---- phase 4: classify 4 channels per thread ----
    const float f0x = scent[0], f0y = scent[1], f1x = scent[2], f1y = scent[3];
    unsigned char* assign_bytes = (unsigned char*)g_assign_words;
#pragma unroll
    for (int j = 0; j < 4; j++) {
        const float dx0 = px[j] - f0x, dy0 = py[j] - f0y;
        const float dx1 = px[j] - f1x, dy1 = py[j] - f1y;
        const int assign =
            ((dx1 * dx1 + dy1 * dy1) < (dx0 * dx0 + dy0 * dy0)) ? 1 : 0;
        assign_bytes[b * C_ + q + 128 * j] = (unsigned char)assign;
    }
}

// ---------------------------------------------------------------------------
// Kernel C: streaming mask split — exact round-2 form (best measured).
// ---------------------------------------------------------------------------
__global__ __launch_bounds__(256) void mask_kernel(
    const float4* __restrict__ in, float4* __restrict__ out0,
    float4* __restrict__ out1)
{
    const int i = blockIdx.x * blockDim.x + threadIdx.x;  // grid covers n4 exactly

    const int c4 = i & (C4_ - 1);
    const int b = i / (C4_ * HW_);

    const unsigned int am = g_assign_words[b * C4_ + c4];
    const float4 x = __ldg(in + i);

    float4 z0, z1;
    const bool m0 = (am & 0x000000ffu) != 0;
    const bool m1 = (am & 0x0000ff00u) != 0;
    const bool m2 = (am & 0x00ff0000u) != 0;
    const bool m3 = (am & 0xff000000u) != 0;
    z1.x = m0 ? x.x : 0.f;  z0.x = m0 ? 0.f : x.x;
    z1.y = m1 ? x.y : 0.f;  z0.y = m1 ? 0.f : x.y;
    z1.z = m2 ? x.z : 0.f;  z0.z = m2 ? 0.f : x.z;
    z1.w = m3 ? x.w : 0.f;  z0.w = m3 ? 0.f : x.w;

    __stcs(out0 + i, z0);
    __stcs(out1 + i, z1);
}

extern "C" void kernel_launch(void* const* d_in, const int* in_sizes, int n_in,
                              void* d_out, int out_size)
{
    const float* in = (const float*)d_in[0];
    float* out = (float*)d_out;
    const int n_elem = B_ * HW_ * C_;  // 12,845,056

    argmax_kmeans_fused<<<dim3(B_, NCHUNK), C4_>>>((const float4*)in);

    const int n4 = n_elem / 4;  // 3,211,264 = 12544 * 256 exactly
    mask_kernel<<<n4 / 256, 256>>>((const float4*)in, (float4*)out,
                                   (float4*)(out + n_elem));
}

// round 16
// speedup vs baseline: 1.0815x; 1.0815x over previous
#include <cuda_runtime.h>
#include <cstdint>
#include <float.h>

#define B_ 128
#define H_ 14
#define W_ 14
#define C_ 512
#define C4_ (C_ / 4)
#define HW_ (H_ * W_)
#define ITERS_ 10
#define NCHUNK 14
#define CHUNKLEN 14   // 196 / 14

// Scratch (device globals: no allocs allowed)
__device__ float4 g_pbest4[B_ * NCHUNK * C4_];
__device__ unsigned int g_pidx4[B_ * NCHUNK * C4_];
__device__ unsigned int g_assign_words[(B_ * C_) / 4];

__device__ __forceinline__ unsigned long long keep_policy() {
    unsigned long long policy;
    asm("createpolicy.fractional.L2::evict_last.b64 %0, 1.0;" : "=l"(policy));
    return policy;
}

__device__ __forceinline__ float4 ldg_keep(const float4* p,
                                           unsigned long long policy) {
    float4 v;
    asm("ld.global.nc.L2::cache_hint.v4.f32 {%0,%1,%2,%3}, [%4], %5;"
        : "=f"(v.x), "=f"(v.y), "=f"(v.z), "=f"(v.w)
        : "l"(p), "l"(policy));
    return v;
}

// ---------------------------------------------------------------------------
// Kernel A: partial spatial argmax, float4-wide, evict_last loads (R11 form,
// best measured 11.4us). grid (B, NCHUNK) = 1792 x 128.
// ---------------------------------------------------------------------------
__global__ __launch_bounds__(C4_) void argmax_partial_kernel(
    const float4* __restrict__ in4)
{
    const int b = blockIdx.x;
    const int chunk = blockIdx.y;
    const int q = threadIdx.x;
    const unsigned long long pol = keep_policy();

    const float4* base = in4 + ((size_t)b * HW_ + chunk * CHUNKLEN) * C4_ + q;
    float bx = -FLT_MAX, by = -FLT_MAX, bz = -FLT_MAX, bw = -FLT_MAX;
    int ix = 0, iy = 0, iz = 0, iw = 0;
#pragma unroll
    for (int i = 0; i < CHUNKLEN; i++) {
        const float4 v = ldg_keep(base + (size_t)i * C4_, pol);
        if (v.x > bx) { bx = v.x; ix = i; }
        if (v.y > by) { by = v.y; iy = i; }
        if (v.z > bz) { bz = v.z; iz = i; }
        if (v.w > bw) { bw = v.w; iw = i; }
    }
    const int o = (b * NCHUNK + chunk) * C4_ + q;
    g_pbest4[o] = make_float4(bx, by, bz, bw);
    g_pidx4[o] = (unsigned int)ix | ((unsigned int)iy << 8) |
                 ((unsigned int)iz << 16) | ((unsigned int)iw << 24);
}

// ---------------------------------------------------------------------------
// Kernel B (PDL secondary): launches while A drains; prologue before the
// grid-dependency sync. Bit-exact k-means as ever. grid = B, 512 threads.
// ---------------------------------------------------------------------------
__global__ __launch_bounds__(C_, 1) void kmeans_kernel()
{
    const int b = blockIdx.x;
    const int c = threadIdx.x;

    __shared__ int hist[HW_];
    __shared__ float sinit[4];
    __shared__ float scent[4];

    // prologue (independent of A)
    if (c < HW_) hist[c] = 0;

    // wait for A's grid to complete before reading partials
    cudaGridDependencySynchronize();

    const float* pbest = (const float*)g_pbest4;
    const unsigned char* pidx = (const unsigned char*)g_pidx4;

    float best = -FLT_MAX;
    int bestIdx = 0;
#pragma unroll
    for (int k = 0; k < NCHUNK; k++) {
        const int o = (b * NCHUNK + k) * C_ + c;
        const float v = pbest[o];
        if (v > best) { best = v; bestIdx = k * CHUNKLEN + (int)pidx[o]; }
    }
    const float px = (float)(bestIdx % W_);
    const float py = (float)(bestIdx / W_);

    if (c == 0) { sinit[0] = px; sinit[1] = py; }
    if (c == 1) { sinit[2] = px; sinit[3] = py; }
    __syncthreads();

    atomicAdd(&hist[bestIdx], 1);
    __syncthreads();

    if (c < 32) {
        int cnt[7]; float bx[7], by[7];
        int sx = 0, sy = 0;
#pragma unroll
        for (int j = 0; j < 7; j++) {
            const int bin = c * 7 + j;
            const int n = (bin < HW_) ? hist[bin] : 0;
            cnt[j] = n;
            bx[j] = (float)(bin % W_);
            by[j] = (float)(bin / W_);
            sx += n * (bin % W_);
            sy += n * (bin / W_);
        }
        const int Sx = __reduce_add_sync(0xffffffffu, sx);
        const int Sy = __reduce_add_sync(0xffffffffu, sy);

        float c0x = sinit[0], c0y = sinit[1];
        float c1x = sinit[2], c1y = sinit[3];

        for (int it = 0; it < ITERS_; it++) {
            int s1x = 0, s1y = 0, n1 = 0;
#pragma unroll
            for (int j = 0; j < 7; j++) {
                const float dx0 = bx[j] - c0x, dy0 = by[j] - c0y;
                const float dx1 = bx[j] - c1x, dy1 = by[j] - c1y;
                const float d0 = dx0 * dx0 + dy0 * dy0;
                const float d1 = dx1 * dx1 + dy1 * dy1;
                const int m = (d1 < d0) ? cnt[j] : 0;
                n1 += m;
                s1x += m * (int)bx[j];
                s1y += m * (int)by[j];
            }
            const int T1x = __reduce_add_sync(0xffffffffu, s1x);
            const int T1y = __reduce_add_sync(0xffffffffu, s1y);
            const int T1n = __reduce_add_sync(0xffffffffu, n1);

            const float inv1 = 1.0f / fmaxf((float)T1n, 1.0f);
            const float inv0 = 1.0f / fmaxf((float)(C_ - T1n), 1.0f);
            // reference swaps clusters each update
            c0x = (float)T1x * inv1; c0y = (float)T1y * inv1;
            c1x = (float)(Sx - T1x) * inv0; c1y = (float)(Sy - T1y) * inv0;
        }
        if (c == 0) { scent[0] = c0x; scent[1] = c0y; scent[2] = c1x; scent[3] = c1y; }
    }
    __syncthreads();

    const float dx0 = px - scent[0], dy0 = py - scent[1];
    const float dx1 = px - scent[2], dy1 = py - scent[3];
    const int assign = ((dx1 * dx1 + dy1 * dy1) < (dx0 * dx0 + dy0 * dy0)) ? 1 : 0;
    ((unsigned char*)g_assign_words)[b * C_ + c] = (unsigned char)assign;
}

// ---------------------------------------------------------------------------
// Kernel C (PDL secondary): input load issues BEFORE the dependency sync, so
// C's 51MB read stream overlaps B's execution. Then mask + streaming stores.
// ---------------------------------------------------------------------------
__global__ __launch_bounds__(256) void mask_kernel(
    const float4* __restrict__ in, float4* __restrict__ out0,
    float4* __restrict__ out1)
{
    const int i = blockIdx.x * blockDim.x + threadIdx.x;  // grid covers n4 exactly

    const int c4 = i & (C4_ - 1);
    const int b = i / (C4_ * HW_);

    // independent of B: start the input read immediately
    const float4 x = __ldg(in + i);

    // wait for B's grid before reading assignments
    cudaGridDependencySynchronize();

    const unsigned int am = g_assign_words[b * C4_ + c4];

    float4 z0, z1;
    const bool m0 = (am & 0x000000ffu) != 0;
    const bool m1 = (am & 0x0000ff00u) != 0;
    const bool m2 = (am & 0x00ff0000u) != 0;
    const bool m3 = (am & 0xff000000u) != 0;
    z1.x = m0 ? x.x : 0.f;  z0.x = m0 ? 0.f : x.x;
    z1.y = m1 ? x.y : 0.f;  z0.y = m1 ? 0.f : x.y;
    z1.z = m2 ? x.z : 0.f;  z0.z = m2 ? 0.f : x.z;
    z1.w = m3 ? x.w : 0.f;  z0.w = m3 ? 0.f : x.w;

    __stcs(out0 + i, z0);
    __stcs(out1 + i, z1);
}

extern "C" void kernel_launch(void* const* d_in, const int* in_sizes, int n_in,
                              void* d_out, int out_size)
{
    const float* in = (const float*)d_in[0];
    float* out = (float*)d_out;
    const int n_elem = B_ * HW_ * C_;  // 12,845,056
    const int n4 = n_elem / 4;         // 3,211,264 = 12544 * 256

    // A: normal launch (implicit PDL trigger at completion)
    argmax_partial_kernel<<<dim3(B_, NCHUNK), C4_>>>((const float4*)in);

    // B and C: programmatic dependent launches (overlap with predecessor)
    cudaLaunchAttribute attr[1];
    attr[0].id = cudaLaunchAttributeProgrammaticStreamSerialization;
    attr[0].val.programmaticStreamSerializationAllowed = 1;

    {
        cudaLaunchConfig_t cfg = {};
        cfg.gridDim = dim3(B_);
        cfg.blockDim = dim3(C_);
        cfg.attrs = attr;
        cfg.numAttrs = 1;
        cudaLaunchKernelEx(&cfg, kmeans_kernel);
    }
    {
        cudaLaunchConfig_t cfg = {};
        cfg.gridDim = dim3(n4 / 256);
        cfg.blockDim = dim3(256);
        cfg.attrs = attr;
        cfg.numAttrs = 1;
        cudaLaunchKernelEx(&cfg, mask_kernel, (const float4*)in, (float4*)out,
                           (float4*)(out + n_elem));
    }
}

// round 17
// speedup vs baseline: 1.1231x; 1.0385x over previous
#include <cuda_runtime.h>
#include <cstdint>
#include <float.h>

#define B_ 128
#define H_ 14
#define W_ 14
#define C_ 512
#define C4_ (C_ / 4)
#define HW_ (H_ * W_)
#define ITERS_ 10
#define NCHUNK 14
#define CHUNKLEN 14   // 196 / 14

// Scratch (device globals: no allocs allowed)
__device__ float4 g_pbest4[B_ * NCHUNK * C4_];
__device__ unsigned int g_pidx4[B_ * NCHUNK * C4_];
__device__ unsigned int g_assign_words[(B_ * C_) / 4];

__device__ __forceinline__ unsigned long long keep_policy() {
    unsigned long long policy;
    asm("createpolicy.fractional.L2::evict_last.b64 %0, 1.0;" : "=l"(policy));
    return policy;
}

__device__ __forceinline__ float4 ldg_keep(const float4* p,
                                           unsigned long long policy) {
    float4 v;
    asm("ld.global.nc.L2::cache_hint.v4.f32 {%0,%1,%2,%3}, [%4], %5;"
        : "=f"(v.x), "=f"(v.y), "=f"(v.z), "=f"(v.w)
        : "l"(p), "l"(policy));
    return v;
}

// ---------------------------------------------------------------------------
// Kernel A: partial spatial argmax, float4-wide, evict_last loads.
// grid (B, NCHUNK) = 1792 x 128. Triggers PDL early so B launches while A's
// tail CTAs drain (B's grid-dependency sync still waits for A completion).
// ---------------------------------------------------------------------------
__global__ __launch_bounds__(C4_) void argmax_partial_kernel(
    const float4* __restrict__ in4)
{
    const int b = blockIdx.x;
    const int chunk = blockIdx.y;
    const int q = threadIdx.x;
    const unsigned long long pol = keep_policy();

    const float4* base = in4 + ((size_t)b * HW_ + chunk * CHUNKLEN) * C4_ + q;
    float bx = -FLT_MAX, by = -FLT_MAX, bz = -FLT_MAX, bw = -FLT_MAX;
    int ix = 0, iy = 0, iz = 0, iw = 0;
#pragma unroll
    for (int i = 0; i < CHUNKLEN; i++) {
        const float4 v = ldg_keep(base + (size_t)i * C4_, pol);
        if (v.x > bx) { bx = v.x; ix = i; }
        if (v.y > by) { by = v.y; iy = i; }
        if (v.z > bz) { bz = v.z; iz = i; }
        if (v.w > bw) { bw = v.w; iw = i; }
    }
    const int o = (b * NCHUNK + chunk) * C4_ + q;
    g_pbest4[o] = make_float4(bx, by, bz, bw);
    g_pidx4[o] = (unsigned int)ix | ((unsigned int)iy << 8) |
                 ((unsigned int)iz << 16) | ((unsigned int)iw << 24);

    cudaTriggerProgrammaticLaunchCompletion();
}

// ---------------------------------------------------------------------------
// Kernel B (PDL secondary): triggers at START so C launches immediately and
// C's independent 51MB input read overlaps B's entire execution. Bit-exact.
// ---------------------------------------------------------------------------
__global__ __launch_bounds__(C_, 1) void kmeans_kernel()
{
    // let C launch right away (C still syncs on B's completion)
    cudaTriggerProgrammaticLaunchCompletion();

    const int b = blockIdx.x;
    const int c = threadIdx.x;

    __shared__ int hist[HW_];
    __shared__ float sinit[4];
    __shared__ float scent[4];

    // prologue (independent of A)
    if (c < HW_) hist[c] = 0;

    // wait for A's grid before reading partials
    cudaGridDependencySynchronize();

    const float* pbest = (const float*)g_pbest4;
    const unsigned char* pidx = (const unsigned char*)g_pidx4;

    float best = -FLT_MAX;
    int bestIdx = 0;
#pragma unroll
    for (int k = 0; k < NCHUNK; k++) {
        const int o = (b * NCHUNK + k) * C_ + c;
        const float v = pbest[o];
        if (v > best) { best = v; bestIdx = k * CHUNKLEN + (int)pidx[o]; }
    }
    const float px = (float)(bestIdx % W_);
    const float py = (float)(bestIdx / W_);

    if (c == 0) { sinit[0] = px; sinit[1] = py; }
    if (c == 1) { sinit[2] = px; sinit[3] = py; }
    __syncthreads();

    atomicAdd(&hist[bestIdx], 1);
    __syncthreads();

    if (c < 32) {
        int cnt[7]; float bx[7], by[7];
        int sx = 0, sy = 0;
#pragma unroll
        for (int j = 0; j < 7; j++) {
            const int bin = c * 7 + j;
            const int n = (bin < HW_) ? hist[bin] : 0;
            cnt[j] = n;
            bx[j] = (float)(bin % W_);
            by[j] = (float)(bin / W_);
            sx += n * (bin % W_);
            sy += n * (bin / W_);
        }
        const int Sx = __reduce_add_sync(0xffffffffu, sx);
        const int Sy = __reduce_add_sync(0xffffffffu, sy);

        float c0x = sinit[0], c0y = sinit[1];
        float c1x = sinit[2], c1y = sinit[3];

        for (int it = 0; it < ITERS_; it++) {
            int s1x = 0, s1y = 0, n1 = 0;
#pragma unroll
            for (int j = 0; j < 7; j++) {
                const float dx0 = bx[j] - c0x, dy0 = by[j] - c0y;
                const float dx1 = bx[j] - c1x, dy1 = by[j] - c1y;
                const float d0 = dx0 * dx0 + dy0 * dy0;
                const float d1 = dx1 * dx1 + dy1 * dy1;
                const int m = (d1 < d0) ? cnt[j] : 0;
                n1 += m;
                s1x += m * (int)bx[j];
                s1y += m * (int)by[j];
            }
            const int T1x = __reduce_add_sync(0xffffffffu, s1x);
            const int T1y = __reduce_add_sync(0xffffffffu, s1y);
            const int T1n = __reduce_add_sync(0xffffffffu, n1);

            const float inv1 = 1.0f / fmaxf((float)T1n, 1.0f);
            const float inv0 = 1.0f / fmaxf((float)(C_ - T1n), 1.0f);
            // reference swaps clusters each update
            c0x = (float)T1x * inv1; c0y = (float)T1y * inv1;
            c1x = (float)(Sx - T1x) * inv0; c1y = (float)(Sy - T1y) * inv0;
        }
        if (c == 0) { scent[0] = c0x; scent[1] = c0y; scent[2] = c1x; scent[3] = c1y; }
    }
    __syncthreads();

    const float dx0 = px - scent[0], dy0 = py - scent[1];
    const float dx1 = px - scent[2], dy1 = py - scent[3];
    const int assign = ((dx1 * dx1 + dy1 * dy1) < (dx0 * dx0 + dy0 * dy0)) ? 1 : 0;
    ((unsigned char*)g_assign_words)[b * C_ + c] = (unsigned char)assign;
}

// ---------------------------------------------------------------------------
// Kernel C (PDL secondary): input load issues BEFORE the dependency sync —
// with B's start-trigger, this read overlaps all of B. Then mask + stcs.
// ---------------------------------------------------------------------------
__global__ __launch_bounds__(256) void mask_kernel(
    const float4* __restrict__ in, float4* __restrict__ out0,
    float4* __restrict__ out1)
{
    const int i = blockIdx.x * blockDim.x + threadIdx.x;  // grid covers n4 exactly

    const int c4 = i & (C4_ - 1);
    const int b = i / (C4_ * HW_);

    // independent of B: start the input read immediately
    const float4 x = __ldg(in + i);

    // wait for B's grid before reading assignments
    cudaGridDependencySynchronize();

    const unsigned int am = g_assign_words[b * C4_ + c4];

    float4 z0, z1;
    const bool m0 = (am & 0x000000ffu) != 0;
    const bool m1 = (am & 0x0000ff00u) != 0;
    const bool m2 = (am & 0x00ff0000u) != 0;
    const bool m3 = (am & 0xff000000u) != 0;
    z1.x = m0 ? x.x : 0.f;  z0.x = m0 ? 0.f : x.x;
    z1.y = m1 ? x.y : 0.f;  z0.y = m1 ? 0.f : x.y;
    z1.z = m2 ? x.z : 0.f;  z0.z = m2 ? 0.f : x.z;
    z1.w = m3 ? x.w : 0.f;  z0.w = m3 ? 0.f : x.w;

    __stcs(out0 + i, z0);
    __stcs(out1 + i, z1);
}

extern "C" void kernel_launch(void* const* d_in, const int* in_sizes, int n_in,
                              void* d_out, int out_size)
{
    const float* in = (const float*)d_in[0];
    float* out = (float*)d_out;
    const int n_elem = B_ * HW_ * C_;  // 12,845,056
    const int n4 = n_elem / 4;         // 3,211,264 = 12544 * 256

    // A: normal launch (explicit early trigger inside)
    argmax_partial_kernel<<<dim3(B_, NCHUNK), C4_>>>((const float4*)in);

    // B and C: programmatic dependent launches
    cudaLaunchAttribute attr[1];
    attr[0].id = cudaLaunchAttributeProgrammaticStreamSerialization;
    attr[0].val.programmaticStreamSerializationAllowed = 1;

    {
        cudaLaunchConfig_t cfg = {};
        cfg.gridDim = dim3(B_);
        cfg.blockDim = dim3(C_);
        cfg.attrs = attr;
        cfg.numAttrs = 1;
        cudaLaunchKernelEx(&cfg, kmeans_kernel);
    }
    {
        cudaLaunchConfig_t cfg = {};
        cfg.gridDim = dim3(n4 / 256);
        cfg.blockDim = dim3(256);
        cfg.attrs = attr;
        cfg.numAttrs = 1;
        cudaLaunchKernelEx(&cfg, mask_kernel, (const float4*)in, (float4*)out,
                           (float4*)(out + n_elem));
    }
}